// round 7
// baseline (speedup 1.0000x reference)
#include <cuda_runtime.h>

// IDCT (DCT-III), B=4096 rows, N=4096. Makhoul + Hermitian-packed 2048-pt
// complex inverse FFT per row. 2048 = 16 * 16 * 8, 128 threads, 16 pts/thread:
//   stage1 radix-16 fused with Z build (x read directly from global)
//   stage2 radix-16, IN-PLACE (read all to regs, sync, write back)
//   stage3 radix-8 (trivial twiddles) fused with output permutation
// SMEM: ONE 2048-float2 buffer (16 KB), XOR-swizzled.
// Twiddles via recurrences (register diet) -> 10 CTAs/SM.

#define NN 4096
#define MM 2048
#define THREADS 128
#define SW(m) ((m) ^ (((m) >> 4) & 15))

__device__ __forceinline__ float2 cadd(float2 a, float2 b) { return make_float2(a.x + b.x, a.y + b.y); }
__device__ __forceinline__ float2 csub(float2 a, float2 b) { return make_float2(a.x - b.x, a.y - b.y); }
__device__ __forceinline__ float2 cmul(float2 a, float2 b) {
    return make_float2(fmaf(a.x, b.x, -a.y * b.y), fmaf(a.x, b.y, a.y * b.x));
}
__device__ __forceinline__ float2 csqr(float2 a) {
    return make_float2(fmaf(a.x, a.x, -a.y * a.y), 2.0f * a.x * a.y);
}

// W_2048^{idx/2} = (e^{+j*pi*idx/8192})^4 ; expk[idx] = (cos t, -sin t)
__device__ __forceinline__ float2 tw_from_expk(const float2* __restrict__ expk, int idx) {
    float2 E = __ldg(&expk[idx]);
    float2 e = make_float2(E.x, -E.y);
    e = csqr(e);
    e = csqr(e);
    return e;
}

// Inverse DFT-8 (+j convention).
__device__ __forceinline__ void idft8(const float2 a[8], float2 X[8]) {
    const float C = 0.70710678118654752f;
    float2 p0 = cadd(a[0], a[4]), m0 = csub(a[0], a[4]);
    float2 q0 = cadd(a[2], a[6]);
    float2 r0 = make_float2(-(a[2].y - a[6].y), a[2].x - a[6].x);
    float2 E0 = cadd(p0, q0), E1 = cadd(m0, r0), E2 = csub(p0, q0), E3 = csub(m0, r0);
    float2 p1 = cadd(a[1], a[5]), m1 = csub(a[1], a[5]);
    float2 q1 = cadd(a[3], a[7]);
    float2 r1 = make_float2(-(a[3].y - a[7].y), a[3].x - a[7].x);
    float2 O0 = cadd(p1, q1), O1 = cadd(m1, r1), O2 = csub(p1, q1), O3 = csub(m1, r1);
    float2 T1 = make_float2(C * (O1.x - O1.y), C * (O1.x + O1.y));
    float2 T2 = make_float2(-O2.y, O2.x);
    float2 T3 = make_float2(-C * (O3.x + O3.y), C * (O3.x - O3.y));
    X[0] = cadd(E0, O0); X[4] = csub(E0, O0);
    X[1] = cadd(E1, T1); X[5] = csub(E1, T1);
    X[2] = cadd(E2, T2); X[6] = csub(E2, T2);
    X[3] = cadd(E3, T3); X[7] = csub(E3, T3);
}

// Inverse DFT-16 (+j), 4x4 split:  n = n0 + 4*n1,  m = m0 + 4*m1.
__device__ __forceinline__ void idft16(const float2 a[16], float2 X[16]) {
    const float C8  = 0.70710678118654752f;
    const float C16 = 0.92387953251128674f;
    const float S16 = 0.38268343236508977f;
    float2 B[4][4];
#pragma unroll
    for (int n0 = 0; n0 < 4; n0++) {
        float2 A0 = a[n0], A1 = a[n0 + 4], A2 = a[n0 + 8], A3 = a[n0 + 12];
        float2 s02 = cadd(A0, A2), d02 = csub(A0, A2);
        float2 s13 = cadd(A1, A3);
        float2 jd13 = make_float2(-(A1.y - A3.y), A1.x - A3.x);
        B[n0][0] = cadd(s02, s13);
        B[n0][1] = cadd(d02, jd13);
        B[n0][2] = csub(s02, s13);
        B[n0][3] = csub(d02, jd13);
    }
    // m0 = 0
    {
        float2 C0 = B[0][0], C1 = B[1][0], C2 = B[2][0], C3 = B[3][0];
        float2 s = cadd(C0, C2), d = csub(C0, C2);
        float2 t = cadd(C1, C3);
        float2 jd13 = make_float2(-(C1.y - C3.y), C1.x - C3.x);
        X[0] = cadd(s, t); X[4] = cadd(d, jd13); X[8] = csub(s, t); X[12] = csub(d, jd13);
    }
    // m0 = 1: twiddles 1, W16, W16^2=(C8,C8), W16^3=(S16,C16)
    {
        float2 C0 = B[0][1];
        float2 C1 = cmul(make_float2(C16, S16), B[1][1]);
        float2 b2 = B[2][1];
        float2 C2 = make_float2(C8 * (b2.x - b2.y), C8 * (b2.x + b2.y));
        float2 C3 = cmul(make_float2(S16, C16), B[3][1]);
        float2 s = cadd(C0, C2), d = csub(C0, C2);
        float2 t = cadd(C1, C3);
        float2 jd13 = make_float2(-(C1.y - C3.y), C1.x - C3.x);
        X[1] = cadd(s, t); X[5] = cadd(d, jd13); X[9] = csub(s, t); X[13] = csub(d, jd13);
    }
    // m0 = 2: twiddles 1, (C8,C8), j, (-C8,C8)
    {
        float2 C0 = B[0][2];
        float2 b1 = B[1][2];
        float2 C1 = make_float2(C8 * (b1.x - b1.y), C8 * (b1.x + b1.y));
        float2 b2 = B[2][2];
        float2 C2 = make_float2(-b2.y, b2.x);
        float2 b3 = B[3][2];
        float2 C3 = make_float2(-C8 * (b3.x + b3.y), C8 * (b3.x - b3.y));
        float2 s = cadd(C0, C2), d = csub(C0, C2);
        float2 t = cadd(C1, C3);
        float2 jd13 = make_float2(-(C1.y - C3.y), C1.x - C3.x);
        X[2] = cadd(s, t); X[6] = cadd(d, jd13); X[10] = csub(s, t); X[14] = csub(d, jd13);
    }
    // m0 = 3: twiddles 1, (S16,C16), (-C8,C8), (-C16,-S16)
    {
        float2 C0 = B[0][3];
        float2 C1 = cmul(make_float2(S16, C16), B[1][3]);
        float2 b2 = B[2][3];
        float2 C2 = make_float2(-C8 * (b2.x + b2.y), C8 * (b2.x - b2.y));
        float2 b3 = B[3][3];
        float2 C3 = make_float2(-fmaf(C16, b3.x, -S16 * b3.y), -fmaf(C16, b3.y, S16 * b3.x));
        float2 s = cadd(C0, C2), d = csub(C0, C2);
        float2 t = cadd(C1, C3);
        float2 jd13 = make_float2(-(C1.y - C3.y), C1.x - C3.x);
        X[3] = cadd(s, t); X[7] = cadd(d, jd13); X[11] = csub(s, t); X[15] = csub(d, jd13);
    }
}

// Apply w1^i via recurrence (only {w, w1} live -> low register pressure)
// and store out[SW(base + i*S)].
__device__ __forceinline__ void tw_store16(float2* __restrict__ out, const float2 X[16],
                                           float2 w1, int base, int S) {
    out[SW(base)]     = X[0];
    out[SW(base + S)] = cmul(w1, X[1]);
    float2 w = w1;
#pragma unroll
    for (int i = 2; i < 16; i++) {
        w = cmul(w, w1);
        out[SW(base + i * S)] = cmul(w, X[i]);
    }
}

__global__ __launch_bounds__(THREADS, 10)
void idct_kernel(const float* __restrict__ x,
                 const float2* __restrict__ expk,
                 float* __restrict__ y) {
    extern __shared__ float2 buf[];   // 2048 float2, in-place via syncs

    const int tid = threadIdx.x;
    const float* xr = x + (size_t)blockIdx.x * NN;
    const float C8 = 0.70710678118654752f;

    // ---- Z build (direct global reads) + radix-16 stage 1 (S=1, p=tid) ----
    {
        float2 Z[16];
        float2 W;                                   // e^{j*2pi*k/4096}, recurrence over i
        const float2 Wstep = make_float2(0.98078528040323044f,   // e^{j*pi/16}
                                         0.19509032201612827f);
#pragma unroll
        for (int i = 0; i < 16; i++) {
            int k = tid + i * THREADS;
            float xk   = xr[k];
            float xnk  = (k == 0) ? 0.0f : xr[NN - k];
            float xmk  = xr[MM - k];
            float xmpk = xr[MM + k];
            float2 E1 = __ldg(&expk[k]);         // (cos t, -sin t), t = pi*k/8192
            float c1 = E1.x, s1 = -E1.y;
            // e^{j*pi*(2048-k)/8192} = e^{j*pi/4} * conj(e^{j*pi*k/8192})
            float c2 = C8 * (c1 + s1), s2 = C8 * (c1 - s1);
            float2 Vk = make_float2(fmaf(xk, c1, xnk * s1), fmaf(xk, s1, -xnk * c1));
            float2 Vm = make_float2(fmaf(xmk, c2, xmpk * s2), fmaf(xmk, s2, -xmpk * c2));
            float2 P = make_float2(Vk.x + Vm.x, Vk.y - Vm.y);   // V_k + conj(V_{M-k})
            float2 Q = make_float2(Vk.x - Vm.x, Vk.y + Vm.y);   // V_k - conj(V_{M-k})
            if (i == 0) W = csqr(csqr(make_float2(c1, s1)));     // e^{j*2pi*tid/4096}
            else        W = cmul(W, Wstep);                      // advance k by 128
            Z[i] = make_float2(P.x - W.y * Q.x - W.x * Q.y,
                               P.y + W.x * Q.x - W.y * Q.y);
        }
        float2 X[16];
        idft16(Z, X);
        float2 w1 = tw_from_expk(expk, 2 * tid);   // W_2048^{tid}
        tw_store16(buf, X, w1, 16 * tid, 1);
    }
    __syncthreads();

    // ---- radix-16 stage 2 (S=16): in-place (regs -> sync -> write) ----
    {
        float2 a[16], X[16];
#pragma unroll
        for (int i = 0; i < 16; i++) a[i] = buf[SW(tid + 128 * i)];
        idft16(a, X);
        int p = tid >> 4, q = tid & 15;
        float2 w1 = tw_from_expk(expk, 32 * p);    // W_2048^{16p}
        __syncthreads();                            // all reads done before writes
        tw_store16(buf, X, w1, q + 256 * p, 16);
    }
    __syncthreads();

    // ---- radix-8 stage 3 (S=256, trivial twiddle) fused with output perm ----
    // Thread handles butterflies b1=tid, b2=255-tid: partner of z_{q+256i}
    // is z_{2047-(q+256i)} = z_{(255-q)+256(7-i)} -> thread-local.
    {
        const int b1 = tid, b2 = 255 - tid;
        float2 a1[8], a2[8], z1[8], z2[8];
#pragma unroll
        for (int i = 0; i < 8; i++) a1[i] = buf[SW(b1 + 256 * i)];
#pragma unroll
        for (int i = 0; i < 8; i++) a2[i] = buf[SW(b2 + 256 * i)];
        idft8(a1, z1);
        idft8(a2, z2);
        // y[4s..4s+3] = {Re z_s, Im z_{2047-s}, Im z_s, Re z_{2047-s}}
        float4* yr = (float4*)(y + (size_t)blockIdx.x * NN);
#pragma unroll
        for (int i = 0; i < 4; i++) {
            yr[b1 + 256 * i] = make_float4(z1[i].x, z2[7 - i].y, z1[i].y, z2[7 - i].x);
            yr[b2 + 256 * i] = make_float4(z2[i].x, z1[7 - i].y, z2[i].y, z1[7 - i].x);
        }
    }
}

extern "C" void kernel_launch(void* const* d_in, const int* in_sizes, int n_in,
                              void* d_out, int out_size) {
    const float*  x    = (const float*)d_in[0];
    const float2* expk = (const float2*)d_in[1];
    float*        y    = (float*)d_out;

    int rows = in_sizes[0] / NN;                 // 4096
    size_t smem_bytes = MM * sizeof(float2);     // 16 KB, single in-place buffer
    idct_kernel<<<rows, THREADS, smem_bytes>>>(x, expk, y);
}

// round 8
// speedup vs baseline: 1.0026x; 1.0026x over previous
#include <cuda_runtime.h>

// IDCT (DCT-III), B=4096 rows, N=4096. Makhoul + Hermitian-packed 2048-pt
// complex inverse FFT per row. 2048 = 16 * 16 * 8, 128 threads, 16 pts/thread:
//   stage1 radix-16 fused with Z build (x read directly from global)
//   stage2 radix-16, IN-PLACE (read all to regs, sync, write back)
//   stage3 radix-8 (trivial twiddles) fused with output permutation
// SMEM: ONE 2048-float2 buffer (16 KB), XOR-swizzled.
// Radix-16 butterfly fused with twiddle+store per m0-block: B[.][m0] dies per
// block and X[16] is never fully materialized -> lower reg peak, 10 CTAs/SM.
// All twiddle values computed exactly as in the R5 squaring tree (no serial
// recurrences -- those regressed in R6/R7).

#define NN 4096
#define MM 2048
#define THREADS 128
#define SW(m) ((m) ^ (((m) >> 4) & 15))

__device__ __forceinline__ float2 cadd(float2 a, float2 b) { return make_float2(a.x + b.x, a.y + b.y); }
__device__ __forceinline__ float2 csub(float2 a, float2 b) { return make_float2(a.x - b.x, a.y - b.y); }
__device__ __forceinline__ float2 cmul(float2 a, float2 b) {
    return make_float2(fmaf(a.x, b.x, -a.y * b.y), fmaf(a.x, b.y, a.y * b.x));
}
__device__ __forceinline__ float2 csqr(float2 a) {
    return make_float2(fmaf(a.x, a.x, -a.y * a.y), 2.0f * a.x * a.y);
}

// W_2048^{idx/2} = (e^{+j*pi*idx/8192})^4 ; expk[idx] = (cos t, -sin t)
__device__ __forceinline__ float2 tw_from_expk(const float2* __restrict__ expk, int idx) {
    float2 E = __ldg(&expk[idx]);
    float2 e = make_float2(E.x, -E.y);
    e = csqr(e);
    e = csqr(e);
    return e;
}

// Inverse DFT-8 (+j convention).
__device__ __forceinline__ void idft8(const float2 a[8], float2 X[8]) {
    const float C = 0.70710678118654752f;
    float2 p0 = cadd(a[0], a[4]), m0 = csub(a[0], a[4]);
    float2 q0 = cadd(a[2], a[6]);
    float2 r0 = make_float2(-(a[2].y - a[6].y), a[2].x - a[6].x);
    float2 E0 = cadd(p0, q0), E1 = cadd(m0, r0), E2 = csub(p0, q0), E3 = csub(m0, r0);
    float2 p1 = cadd(a[1], a[5]), m1 = csub(a[1], a[5]);
    float2 q1 = cadd(a[3], a[7]);
    float2 r1 = make_float2(-(a[3].y - a[7].y), a[3].x - a[7].x);
    float2 O0 = cadd(p1, q1), O1 = cadd(m1, r1), O2 = csub(p1, q1), O3 = csub(m1, r1);
    float2 T1 = make_float2(C * (O1.x - O1.y), C * (O1.x + O1.y));
    float2 T2 = make_float2(-O2.y, O2.x);
    float2 T3 = make_float2(-C * (O3.x + O3.y), C * (O3.x - O3.y));
    X[0] = cadd(E0, O0); X[4] = csub(E0, O0);
    X[1] = cadd(E1, T1); X[5] = csub(E1, T1);
    X[2] = cadd(E2, T2); X[6] = csub(E2, T2);
    X[3] = cadd(E3, T3); X[7] = csub(E3, T3);
}

// Inverse DFT-16 (+j) FUSED with twiddle application (w1^m) and swizzled
// store: out[SW(base + m*S)] = w1^m * X_m.  4x4 split, n = n0 + 4*n1,
// m = m0 + 4*m1. Each m0 block stores immediately (minimizes liveness).
__device__ __forceinline__ void idft16_store(float2* __restrict__ out, const float2 a[16],
                                             float2 w1, int base, int S) {
    const float C8  = 0.70710678118654752f;
    const float C16 = 0.92387953251128674f;
    const float S16 = 0.38268343236508977f;
    float2 B[4][4];
#pragma unroll
    for (int n0 = 0; n0 < 4; n0++) {
        float2 A0 = a[n0], A1 = a[n0 + 4], A2 = a[n0 + 8], A3 = a[n0 + 12];
        float2 s02 = cadd(A0, A2), d02 = csub(A0, A2);
        float2 s13 = cadd(A1, A3);
        float2 jd13 = make_float2(-(A1.y - A3.y), A1.x - A3.x);
        B[n0][0] = cadd(s02, s13);
        B[n0][1] = cadd(d02, jd13);
        B[n0][2] = csub(s02, s13);
        B[n0][3] = csub(d02, jd13);
    }
    // Twiddle tree (depth <= 2 from w1; same values as R5)
    float2 w2  = csqr(w1);
    float2 w4  = csqr(w2);
    float2 w8  = csqr(w4);
    float2 w3  = cmul(w1, w2);
    float2 w12 = cmul(w4, w8);
    // m0 = 0: outputs m = 0,4,8,12; twiddles 1, w4, w8, w12
    {
        float2 C0 = B[0][0], C1 = B[1][0], C2 = B[2][0], C3 = B[3][0];
        float2 s = cadd(C0, C2), d = csub(C0, C2);
        float2 t = cadd(C1, C3);
        float2 jd = make_float2(-(C1.y - C3.y), C1.x - C3.x);
        out[SW(base)]          = cadd(s, t);
        out[SW(base + 4 * S)]  = cmul(w4,  cadd(d, jd));
        out[SW(base + 8 * S)]  = cmul(w8,  csub(s, t));
        out[SW(base + 12 * S)] = cmul(w12, csub(d, jd));
    }
    // m0 = 1: W16 factors 1, (C16,S16), (C8,C8), (S16,C16); twiddles w1*{1,w4,w8,w12}
    {
        float2 C0 = B[0][1];
        float2 C1 = cmul(make_float2(C16, S16), B[1][1]);
        float2 b2 = B[2][1];
        float2 C2 = make_float2(C8 * (b2.x - b2.y), C8 * (b2.x + b2.y));
        float2 C3 = cmul(make_float2(S16, C16), B[3][1]);
        float2 s = cadd(C0, C2), d = csub(C0, C2);
        float2 t = cadd(C1, C3);
        float2 jd = make_float2(-(C1.y - C3.y), C1.x - C3.x);
        out[SW(base + S)]      = cmul(w1, cadd(s, t));
        out[SW(base + 5 * S)]  = cmul(cmul(w1, w4),  cadd(d, jd));
        out[SW(base + 9 * S)]  = cmul(cmul(w1, w8),  csub(s, t));
        out[SW(base + 13 * S)] = cmul(cmul(w1, w12), csub(d, jd));
    }
    // m0 = 2: W16 factors 1, (C8,C8), j, (-C8,C8); twiddles w2*{1,w4,w8,w12}
    {
        float2 C0 = B[0][2];
        float2 b1 = B[1][2];
        float2 C1 = make_float2(C8 * (b1.x - b1.y), C8 * (b1.x + b1.y));
        float2 b2 = B[2][2];
        float2 C2 = make_float2(-b2.y, b2.x);
        float2 b3 = B[3][2];
        float2 C3 = make_float2(-C8 * (b3.x + b3.y), C8 * (b3.x - b3.y));
        float2 s = cadd(C0, C2), d = csub(C0, C2);
        float2 t = cadd(C1, C3);
        float2 jd = make_float2(-(C1.y - C3.y), C1.x - C3.x);
        out[SW(base + 2 * S)]  = cmul(w2, cadd(s, t));
        out[SW(base + 6 * S)]  = cmul(cmul(w2, w4),  cadd(d, jd));
        out[SW(base + 10 * S)] = cmul(cmul(w2, w8),  csub(s, t));
        out[SW(base + 14 * S)] = cmul(cmul(w2, w12), csub(d, jd));
    }
    // m0 = 3: W16 factors 1, (S16,C16), (-C8,C8), -(C16,S16); twiddles w3*{1,w4,w8,w12}
    {
        float2 C0 = B[0][3];
        float2 C1 = cmul(make_float2(S16, C16), B[1][3]);
        float2 b2 = B[2][3];
        float2 C2 = make_float2(-C8 * (b2.x + b2.y), C8 * (b2.x - b2.y));
        float2 b3 = B[3][3];
        float2 C3 = make_float2(-fmaf(C16, b3.x, -S16 * b3.y), -fmaf(C16, b3.y, S16 * b3.x));
        float2 s = cadd(C0, C2), d = csub(C0, C2);
        float2 t = cadd(C1, C3);
        float2 jd = make_float2(-(C1.y - C3.y), C1.x - C3.x);
        out[SW(base + 3 * S)]  = cmul(w3, cadd(s, t));
        out[SW(base + 7 * S)]  = cmul(cmul(w3, w4),  cadd(d, jd));
        out[SW(base + 11 * S)] = cmul(cmul(w3, w8),  csub(s, t));
        out[SW(base + 15 * S)] = cmul(cmul(w3, w12), csub(d, jd));
    }
}

__global__ __launch_bounds__(THREADS, 10)
void idct_kernel(const float* __restrict__ x,
                 const float2* __restrict__ expk,
                 float* __restrict__ y) {
    extern __shared__ float2 buf[];   // 2048 float2, in-place via syncs

    const int tid = threadIdx.x;
    const float* xr = x + (size_t)blockIdx.x * NN;
    const float C8 = 0.70710678118654752f;

    // ---- Z build (direct global reads) + radix-16 stage 1 (S=1, p=tid) ----
    {
        float2 Z[16];
#pragma unroll
        for (int i = 0; i < 16; i++) {
            int k = tid + i * THREADS;
            float xk   = xr[k];
            float xnk  = (k == 0) ? 0.0f : xr[NN - k];
            float xmk  = xr[MM - k];
            float xmpk = xr[MM + k];
            float2 E1 = __ldg(&expk[k]);         // (cos t, -sin t), t = pi*k/8192
            float c1 = E1.x, s1 = -E1.y;
            // e^{j*pi*(2048-k)/8192} = e^{j*pi/4} * conj(e^{j*pi*k/8192})
            float c2 = C8 * (c1 + s1), s2 = C8 * (c1 - s1);
            float2 Vk = make_float2(fmaf(xk, c1, xnk * s1), fmaf(xk, s1, -xnk * c1));
            float2 Vm = make_float2(fmaf(xmk, c2, xmpk * s2), fmaf(xmk, s2, -xmpk * c2));
            float2 P = make_float2(Vk.x + Vm.x, Vk.y - Vm.y);   // V_k + conj(V_{M-k})
            float2 Q = make_float2(Vk.x - Vm.x, Vk.y + Vm.y);   // V_k - conj(V_{M-k})
            float2 W = csqr(csqr(make_float2(c1, s1)));          // e^{j*2pi*k/4096}, independent per i
            Z[i] = make_float2(P.x - W.y * Q.x - W.x * Q.y,
                               P.y + W.x * Q.x - W.y * Q.y);
        }
        float2 w1 = tw_from_expk(expk, 2 * tid);   // W_2048^{tid}
        idft16_store(buf, Z, w1, 16 * tid, 1);
    }
    __syncthreads();

    // ---- radix-16 stage 2 (S=16): in-place (regs -> sync -> write) ----
    {
        float2 a[16];
#pragma unroll
        for (int i = 0; i < 16; i++) a[i] = buf[SW(tid + 128 * i)];
        int p = tid >> 4, q = tid & 15;
        float2 w1 = tw_from_expk(expk, 32 * p);    // W_2048^{16p}
        __syncthreads();                            // all reads done before writes
        idft16_store(buf, a, w1, q + 256 * p, 16);
    }
    __syncthreads();

    // ---- radix-8 stage 3 (S=256, trivial twiddle) fused with output perm ----
    // Thread handles butterflies b1=tid, b2=255-tid: partner of z_{q+256i}
    // is z_{2047-(q+256i)} = z_{(255-q)+256(7-i)} -> thread-local.
    {
        const int b1 = tid, b2 = 255 - tid;
        float2 a1[8], a2[8], z1[8], z2[8];
#pragma unroll
        for (int i = 0; i < 8; i++) a1[i] = buf[SW(b1 + 256 * i)];
#pragma unroll
        for (int i = 0; i < 8; i++) a2[i] = buf[SW(b2 + 256 * i)];
        idft8(a1, z1);
        idft8(a2, z2);
        // y[4s..4s+3] = {Re z_s, Im z_{2047-s}, Im z_s, Re z_{2047-s}}
        float4* yr = (float4*)(y + (size_t)blockIdx.x * NN);
#pragma unroll
        for (int i = 0; i < 4; i++) {
            yr[b1 + 256 * i] = make_float4(z1[i].x, z2[7 - i].y, z1[i].y, z2[7 - i].x);
            yr[b2 + 256 * i] = make_float4(z2[i].x, z1[7 - i].y, z2[i].y, z1[7 - i].x);
        }
    }
}

extern "C" void kernel_launch(void* const* d_in, const int* in_sizes, int n_in,
                              void* d_out, int out_size) {
    const float*  x    = (const float*)d_in[0];
    const float2* expk = (const float2*)d_in[1];
    float*        y    = (float*)d_out;

    int rows = in_sizes[0] / NN;                 // 4096
    size_t smem_bytes = MM * sizeof(float2);     // 16 KB, single in-place buffer
    idct_kernel<<<rows, THREADS, smem_bytes>>>(x, expk, y);
}

// round 9
// speedup vs baseline: 1.0235x; 1.0209x over previous
#include <cuda_runtime.h>

// IDCT (DCT-III), B=4096 rows, N=4096. Makhoul + Hermitian-packed 2048-pt
// complex inverse FFT per row. 2048 = 16 * 16 * 8, 128 threads, 16 pts/thread:
//   stage1 radix-16 fused with Z build (x read directly from global)
//   stage2 radix-16, IN-PLACE (read all to regs, sync, write back)
//   stage3 radix-8 (trivial twiddles) fused with output permutation
// SMEM: ONE 2048-float2 buffer (16 KB), XOR-swizzled.
// Fused butterfly+twiddle+store (R8) at the R5 register budget (bound 9):
// bound-10's 48-reg cap regressed the schedule; 56 regs is the sweet spot.
// Twiddle-base LDGs for BOTH stages prefetched at kernel entry so the
// stage-2 LDG latency is not exposed in the post-barrier convoy.

#define NN 4096
#define MM 2048
#define THREADS 128
#define SW(m) ((m) ^ (((m) >> 4) & 15))

__device__ __forceinline__ float2 cadd(float2 a, float2 b) { return make_float2(a.x + b.x, a.y + b.y); }
__device__ __forceinline__ float2 csub(float2 a, float2 b) { return make_float2(a.x - b.x, a.y - b.y); }
__device__ __forceinline__ float2 cmul(float2 a, float2 b) {
    return make_float2(fmaf(a.x, b.x, -a.y * b.y), fmaf(a.x, b.y, a.y * b.x));
}
__device__ __forceinline__ float2 csqr(float2 a) {
    return make_float2(fmaf(a.x, a.x, -a.y * a.y), 2.0f * a.x * a.y);
}

// (e^{+j t})^4 from expk value E = (cos t, -sin t):  W_2048^{idx/2} for idx arg.
__device__ __forceinline__ float2 pow4_conj(float2 E) {
    float2 e = make_float2(E.x, -E.y);
    e = csqr(e);
    e = csqr(e);
    return e;
}

// Inverse DFT-8 (+j convention).
__device__ __forceinline__ void idft8(const float2 a[8], float2 X[8]) {
    const float C = 0.70710678118654752f;
    float2 p0 = cadd(a[0], a[4]), m0 = csub(a[0], a[4]);
    float2 q0 = cadd(a[2], a[6]);
    float2 r0 = make_float2(-(a[2].y - a[6].y), a[2].x - a[6].x);
    float2 E0 = cadd(p0, q0), E1 = cadd(m0, r0), E2 = csub(p0, q0), E3 = csub(m0, r0);
    float2 p1 = cadd(a[1], a[5]), m1 = csub(a[1], a[5]);
    float2 q1 = cadd(a[3], a[7]);
    float2 r1 = make_float2(-(a[3].y - a[7].y), a[3].x - a[7].x);
    float2 O0 = cadd(p1, q1), O1 = cadd(m1, r1), O2 = csub(p1, q1), O3 = csub(m1, r1);
    float2 T1 = make_float2(C * (O1.x - O1.y), C * (O1.x + O1.y));
    float2 T2 = make_float2(-O2.y, O2.x);
    float2 T3 = make_float2(-C * (O3.x + O3.y), C * (O3.x - O3.y));
    X[0] = cadd(E0, O0); X[4] = csub(E0, O0);
    X[1] = cadd(E1, T1); X[5] = csub(E1, T1);
    X[2] = cadd(E2, T2); X[6] = csub(E2, T2);
    X[3] = cadd(E3, T3); X[7] = csub(E3, T3);
}

// Inverse DFT-16 (+j) FUSED with twiddle application (w1^m) and swizzled
// store: out[SW(base + m*S)] = w1^m * X_m.  4x4 split, n = n0 + 4*n1,
// m = m0 + 4*m1. Each m0 block stores immediately (minimizes liveness).
__device__ __forceinline__ void idft16_store(float2* __restrict__ out, const float2 a[16],
                                             float2 w1, int base, int S) {
    const float C8  = 0.70710678118654752f;
    const float C16 = 0.92387953251128674f;
    const float S16 = 0.38268343236508977f;
    float2 B[4][4];
#pragma unroll
    for (int n0 = 0; n0 < 4; n0++) {
        float2 A0 = a[n0], A1 = a[n0 + 4], A2 = a[n0 + 8], A3 = a[n0 + 12];
        float2 s02 = cadd(A0, A2), d02 = csub(A0, A2);
        float2 s13 = cadd(A1, A3);
        float2 jd13 = make_float2(-(A1.y - A3.y), A1.x - A3.x);
        B[n0][0] = cadd(s02, s13);
        B[n0][1] = cadd(d02, jd13);
        B[n0][2] = csub(s02, s13);
        B[n0][3] = csub(d02, jd13);
    }
    // Twiddle tree (depth <= 2 from w1)
    float2 w2  = csqr(w1);
    float2 w4  = csqr(w2);
    float2 w8  = csqr(w4);
    float2 w3  = cmul(w1, w2);
    float2 w12 = cmul(w4, w8);
    // m0 = 0: outputs m = 0,4,8,12; twiddles 1, w4, w8, w12
    {
        float2 C0 = B[0][0], C1 = B[1][0], C2 = B[2][0], C3 = B[3][0];
        float2 s = cadd(C0, C2), d = csub(C0, C2);
        float2 t = cadd(C1, C3);
        float2 jd = make_float2(-(C1.y - C3.y), C1.x - C3.x);
        out[SW(base)]          = cadd(s, t);
        out[SW(base + 4 * S)]  = cmul(w4,  cadd(d, jd));
        out[SW(base + 8 * S)]  = cmul(w8,  csub(s, t));
        out[SW(base + 12 * S)] = cmul(w12, csub(d, jd));
    }
    // m0 = 1: W16 factors 1, (C16,S16), (C8,C8), (S16,C16); twiddles w1*{1,w4,w8,w12}
    {
        float2 C0 = B[0][1];
        float2 C1 = cmul(make_float2(C16, S16), B[1][1]);
        float2 b2 = B[2][1];
        float2 C2 = make_float2(C8 * (b2.x - b2.y), C8 * (b2.x + b2.y));
        float2 C3 = cmul(make_float2(S16, C16), B[3][1]);
        float2 s = cadd(C0, C2), d = csub(C0, C2);
        float2 t = cadd(C1, C3);
        float2 jd = make_float2(-(C1.y - C3.y), C1.x - C3.x);
        out[SW(base + S)]      = cmul(w1, cadd(s, t));
        out[SW(base + 5 * S)]  = cmul(cmul(w1, w4),  cadd(d, jd));
        out[SW(base + 9 * S)]  = cmul(cmul(w1, w8),  csub(s, t));
        out[SW(base + 13 * S)] = cmul(cmul(w1, w12), csub(d, jd));
    }
    // m0 = 2: W16 factors 1, (C8,C8), j, (-C8,C8); twiddles w2*{1,w4,w8,w12}
    {
        float2 C0 = B[0][2];
        float2 b1 = B[1][2];
        float2 C1 = make_float2(C8 * (b1.x - b1.y), C8 * (b1.x + b1.y));
        float2 b2 = B[2][2];
        float2 C2 = make_float2(-b2.y, b2.x);
        float2 b3 = B[3][2];
        float2 C3 = make_float2(-C8 * (b3.x + b3.y), C8 * (b3.x - b3.y));
        float2 s = cadd(C0, C2), d = csub(C0, C2);
        float2 t = cadd(C1, C3);
        float2 jd = make_float2(-(C1.y - C3.y), C1.x - C3.x);
        out[SW(base + 2 * S)]  = cmul(w2, cadd(s, t));
        out[SW(base + 6 * S)]  = cmul(cmul(w2, w4),  cadd(d, jd));
        out[SW(base + 10 * S)] = cmul(cmul(w2, w8),  csub(s, t));
        out[SW(base + 14 * S)] = cmul(cmul(w2, w12), csub(d, jd));
    }
    // m0 = 3: W16 factors 1, (S16,C16), (-C8,C8), -(C16,S16); twiddles w3*{1,w4,w8,w12}
    {
        float2 C0 = B[0][3];
        float2 C1 = cmul(make_float2(S16, C16), B[1][3]);
        float2 b2 = B[2][3];
        float2 C2 = make_float2(-C8 * (b2.x + b2.y), C8 * (b2.x - b2.y));
        float2 b3 = B[3][3];
        float2 C3 = make_float2(-fmaf(C16, b3.x, -S16 * b3.y), -fmaf(C16, b3.y, S16 * b3.x));
        float2 s = cadd(C0, C2), d = csub(C0, C2);
        float2 t = cadd(C1, C3);
        float2 jd = make_float2(-(C1.y - C3.y), C1.x - C3.x);
        out[SW(base + 3 * S)]  = cmul(w3, cadd(s, t));
        out[SW(base + 7 * S)]  = cmul(cmul(w3, w4),  cadd(d, jd));
        out[SW(base + 11 * S)] = cmul(cmul(w3, w8),  csub(s, t));
        out[SW(base + 15 * S)] = cmul(cmul(w3, w12), csub(d, jd));
    }
}

__global__ __launch_bounds__(THREADS, 9)
void idct_kernel(const float* __restrict__ x,
                 const float2* __restrict__ expk,
                 float* __restrict__ y) {
    extern __shared__ float2 buf[];   // 2048 float2, in-place via syncs

    const int tid = threadIdx.x;
    const float* xr = x + (size_t)blockIdx.x * NN;
    const float C8 = 0.70710678118654752f;

    // Prefetch both stages' twiddle-base expk values NOW: their ~600cyc LDG
    // latency overlaps the Z-build load burst instead of the post-barrier gap.
    float2 E_s1 = __ldg(&expk[2 * tid]);               // -> W_2048^{tid}
    float2 E_s2 = __ldg(&expk[32 * (tid >> 4)]);       // -> W_2048^{16*(tid>>4)}

    // ---- Z build (direct global reads) + radix-16 stage 1 (S=1, p=tid) ----
    {
        float2 Z[16];
#pragma unroll
        for (int i = 0; i < 16; i++) {
            int k = tid + i * THREADS;
            float xk   = xr[k];
            float xnk  = (k == 0) ? 0.0f : xr[NN - k];
            float xmk  = xr[MM - k];
            float xmpk = xr[MM + k];
            float2 E1 = __ldg(&expk[k]);         // (cos t, -sin t), t = pi*k/8192
            float c1 = E1.x, s1 = -E1.y;
            // e^{j*pi*(2048-k)/8192} = e^{j*pi/4} * conj(e^{j*pi*k/8192})
            float c2 = C8 * (c1 + s1), s2 = C8 * (c1 - s1);
            float2 Vk = make_float2(fmaf(xk, c1, xnk * s1), fmaf(xk, s1, -xnk * c1));
            float2 Vm = make_float2(fmaf(xmk, c2, xmpk * s2), fmaf(xmk, s2, -xmpk * c2));
            float2 P = make_float2(Vk.x + Vm.x, Vk.y - Vm.y);   // V_k + conj(V_{M-k})
            float2 Q = make_float2(Vk.x - Vm.x, Vk.y + Vm.y);   // V_k - conj(V_{M-k})
            float2 W = csqr(csqr(make_float2(c1, s1)));          // e^{j*2pi*k/4096}, independent per i
            Z[i] = make_float2(P.x - W.y * Q.x - W.x * Q.y,
                               P.y + W.x * Q.x - W.y * Q.y);
        }
        idft16_store(buf, Z, pow4_conj(E_s1), 16 * tid, 1);
    }
    __syncthreads();

    // ---- radix-16 stage 2 (S=16): in-place (regs -> sync -> write) ----
    {
        float2 a[16];
#pragma unroll
        for (int i = 0; i < 16; i++) a[i] = buf[SW(tid + 128 * i)];
        int p = tid >> 4, q = tid & 15;
        float2 w1 = pow4_conj(E_s2);               // W_2048^{16p}
        __syncthreads();                            // all reads done before writes
        idft16_store(buf, a, w1, q + 256 * p, 16);
    }
    __syncthreads();

    // ---- radix-8 stage 3 (S=256, trivial twiddle) fused with output perm ----
    // Thread handles butterflies b1=tid, b2=255-tid: partner of z_{q+256i}
    // is z_{2047-(q+256i)} = z_{(255-q)+256(7-i)} -> thread-local.
    {
        const int b1 = tid, b2 = 255 - tid;
        float2 a1[8], a2[8], z1[8], z2[8];
#pragma unroll
        for (int i = 0; i < 8; i++) a1[i] = buf[SW(b1 + 256 * i)];
#pragma unroll
        for (int i = 0; i < 8; i++) a2[i] = buf[SW(b2 + 256 * i)];
        idft8(a1, z1);
        idft8(a2, z2);
        // y[4s..4s+3] = {Re z_s, Im z_{2047-s}, Im z_s, Re z_{2047-s}}
        float4* yr = (float4*)(y + (size_t)blockIdx.x * NN);
#pragma unroll
        for (int i = 0; i < 4; i++) {
            yr[b1 + 256 * i] = make_float4(z1[i].x, z2[7 - i].y, z1[i].y, z2[7 - i].x);
            yr[b2 + 256 * i] = make_float4(z2[i].x, z1[7 - i].y, z2[i].y, z1[7 - i].x);
        }
    }
}

extern "C" void kernel_launch(void* const* d_in, const int* in_sizes, int n_in,
                              void* d_out, int out_size) {
    const float*  x    = (const float*)d_in[0];
    const float2* expk = (const float2*)d_in[1];
    float*        y    = (float*)d_out;

    int rows = in_sizes[0] / NN;                 // 4096
    size_t smem_bytes = MM * sizeof(float2);     // 16 KB, single in-place buffer
    idct_kernel<<<rows, THREADS, smem_bytes>>>(x, expk, y);
}

// round 10
// speedup vs baseline: 1.0671x; 1.0426x over previous
#include <cuda_runtime.h>

// IDCT (DCT-III), B=4096 rows, N=4096. Makhoul + Hermitian-packed 2048-pt
// complex inverse FFT per row. 2048 = 16 * 16 * 8, 128 threads, 16 pts/thread:
//   stage1 radix-16 fused with Z build (x read directly from global)
//   stage2 radix-16, IN-PLACE (read all to regs, sync, write back)
//   stage3 radix-8 (trivial twiddles) fused with output permutation
// SMEM: ONE 2048-float2 buffer (16 KB), XOR-swizzled. bound-9 (56-reg budget).
// FLOP cuts (exact identities):
//   - stage twiddles w1 loaded directly: W_2048^t = flip(expk[8t])
//   - Z build processes k and k+1024 as a pair: W_{k+1024} = j*W_k

#define NN 4096
#define MM 2048
#define THREADS 128
#define SW(m) ((m) ^ (((m) >> 4) & 15))

__device__ __forceinline__ float2 cadd(float2 a, float2 b) { return make_float2(a.x + b.x, a.y + b.y); }
__device__ __forceinline__ float2 csub(float2 a, float2 b) { return make_float2(a.x - b.x, a.y - b.y); }
__device__ __forceinline__ float2 cmul(float2 a, float2 b) {
    return make_float2(fmaf(a.x, b.x, -a.y * b.y), fmaf(a.x, b.y, a.y * b.x));
}
__device__ __forceinline__ float2 csqr(float2 a) {
    return make_float2(fmaf(a.x, a.x, -a.y * a.y), 2.0f * a.x * a.y);
}

// Inverse DFT-8 (+j convention).
__device__ __forceinline__ void idft8(const float2 a[8], float2 X[8]) {
    const float C = 0.70710678118654752f;
    float2 p0 = cadd(a[0], a[4]), m0 = csub(a[0], a[4]);
    float2 q0 = cadd(a[2], a[6]);
    float2 r0 = make_float2(-(a[2].y - a[6].y), a[2].x - a[6].x);
    float2 E0 = cadd(p0, q0), E1 = cadd(m0, r0), E2 = csub(p0, q0), E3 = csub(m0, r0);
    float2 p1 = cadd(a[1], a[5]), m1 = csub(a[1], a[5]);
    float2 q1 = cadd(a[3], a[7]);
    float2 r1 = make_float2(-(a[3].y - a[7].y), a[3].x - a[7].x);
    float2 O0 = cadd(p1, q1), O1 = cadd(m1, r1), O2 = csub(p1, q1), O3 = csub(m1, r1);
    float2 T1 = make_float2(C * (O1.x - O1.y), C * (O1.x + O1.y));
    float2 T2 = make_float2(-O2.y, O2.x);
    float2 T3 = make_float2(-C * (O3.x + O3.y), C * (O3.x - O3.y));
    X[0] = cadd(E0, O0); X[4] = csub(E0, O0);
    X[1] = cadd(E1, T1); X[5] = csub(E1, T1);
    X[2] = cadd(E2, T2); X[6] = csub(E2, T2);
    X[3] = cadd(E3, T3); X[7] = csub(E3, T3);
}

// Inverse DFT-16 (+j) FUSED with twiddle application (w1^m) and swizzled
// store: out[SW(base + m*S)] = w1^m * X_m.  4x4 split, n = n0 + 4*n1,
// m = m0 + 4*m1. Each m0 block stores immediately (minimizes liveness).
__device__ __forceinline__ void idft16_store(float2* __restrict__ out, const float2 a[16],
                                             float2 w1, int base, int S) {
    const float C8  = 0.70710678118654752f;
    const float C16 = 0.92387953251128674f;
    const float S16 = 0.38268343236508977f;
    float2 B[4][4];
#pragma unroll
    for (int n0 = 0; n0 < 4; n0++) {
        float2 A0 = a[n0], A1 = a[n0 + 4], A2 = a[n0 + 8], A3 = a[n0 + 12];
        float2 s02 = cadd(A0, A2), d02 = csub(A0, A2);
        float2 s13 = cadd(A1, A3);
        float2 jd13 = make_float2(-(A1.y - A3.y), A1.x - A3.x);
        B[n0][0] = cadd(s02, s13);
        B[n0][1] = cadd(d02, jd13);
        B[n0][2] = csub(s02, s13);
        B[n0][3] = csub(d02, jd13);
    }
    // Twiddle tree (depth <= 2 from w1)
    float2 w2  = csqr(w1);
    float2 w4  = csqr(w2);
    float2 w8  = csqr(w4);
    float2 w3  = cmul(w1, w2);
    float2 w12 = cmul(w4, w8);
    // m0 = 0: outputs m = 0,4,8,12; twiddles 1, w4, w8, w12
    {
        float2 C0 = B[0][0], C1 = B[1][0], C2 = B[2][0], C3 = B[3][0];
        float2 s = cadd(C0, C2), d = csub(C0, C2);
        float2 t = cadd(C1, C3);
        float2 jd = make_float2(-(C1.y - C3.y), C1.x - C3.x);
        out[SW(base)]          = cadd(s, t);
        out[SW(base + 4 * S)]  = cmul(w4,  cadd(d, jd));
        out[SW(base + 8 * S)]  = cmul(w8,  csub(s, t));
        out[SW(base + 12 * S)] = cmul(w12, csub(d, jd));
    }
    // m0 = 1
    {
        float2 C0 = B[0][1];
        float2 C1 = cmul(make_float2(C16, S16), B[1][1]);
        float2 b2 = B[2][1];
        float2 C2 = make_float2(C8 * (b2.x - b2.y), C8 * (b2.x + b2.y));
        float2 C3 = cmul(make_float2(S16, C16), B[3][1]);
        float2 s = cadd(C0, C2), d = csub(C0, C2);
        float2 t = cadd(C1, C3);
        float2 jd = make_float2(-(C1.y - C3.y), C1.x - C3.x);
        out[SW(base + S)]      = cmul(w1, cadd(s, t));
        out[SW(base + 5 * S)]  = cmul(cmul(w1, w4),  cadd(d, jd));
        out[SW(base + 9 * S)]  = cmul(cmul(w1, w8),  csub(s, t));
        out[SW(base + 13 * S)] = cmul(cmul(w1, w12), csub(d, jd));
    }
    // m0 = 2
    {
        float2 C0 = B[0][2];
        float2 b1 = B[1][2];
        float2 C1 = make_float2(C8 * (b1.x - b1.y), C8 * (b1.x + b1.y));
        float2 b2 = B[2][2];
        float2 C2 = make_float2(-b2.y, b2.x);
        float2 b3 = B[3][2];
        float2 C3 = make_float2(-C8 * (b3.x + b3.y), C8 * (b3.x - b3.y));
        float2 s = cadd(C0, C2), d = csub(C0, C2);
        float2 t = cadd(C1, C3);
        float2 jd = make_float2(-(C1.y - C3.y), C1.x - C3.x);
        out[SW(base + 2 * S)]  = cmul(w2, cadd(s, t));
        out[SW(base + 6 * S)]  = cmul(cmul(w2, w4),  cadd(d, jd));
        out[SW(base + 10 * S)] = cmul(cmul(w2, w8),  csub(s, t));
        out[SW(base + 14 * S)] = cmul(cmul(w2, w12), csub(d, jd));
    }
    // m0 = 3
    {
        float2 C0 = B[0][3];
        float2 C1 = cmul(make_float2(S16, C16), B[1][3]);
        float2 b2 = B[2][3];
        float2 C2 = make_float2(-C8 * (b2.x + b2.y), C8 * (b2.x - b2.y));
        float2 b3 = B[3][3];
        float2 C3 = make_float2(-fmaf(C16, b3.x, -S16 * b3.y), -fmaf(C16, b3.y, S16 * b3.x));
        float2 s = cadd(C0, C2), d = csub(C0, C2);
        float2 t = cadd(C1, C3);
        float2 jd = make_float2(-(C1.y - C3.y), C1.x - C3.x);
        out[SW(base + 3 * S)]  = cmul(w3, cadd(s, t));
        out[SW(base + 7 * S)]  = cmul(cmul(w3, w4),  cadd(d, jd));
        out[SW(base + 11 * S)] = cmul(cmul(w3, w8),  csub(s, t));
        out[SW(base + 15 * S)] = cmul(cmul(w3, w12), csub(d, jd));
    }
}

// One half-element of the Z build: given x quartet, expk entry E, and the
// rotation W (= e^{j*2pi*k/4096} or j*that), produce Z_k.
__device__ __forceinline__ float2 z_elem(float xk, float xnk, float xmk, float xmpk,
                                         float2 E, float2 W, float C8) {
    float c1 = E.x, s1 = -E.y;
    // e^{j*pi*(2048-k)/8192} = e^{j*pi/4} * conj(e^{j*pi*k/8192})
    float c2 = C8 * (c1 + s1), s2 = C8 * (c1 - s1);
    float2 Vk = make_float2(fmaf(xk, c1, xnk * s1), fmaf(xk, s1, -xnk * c1));
    float2 Vm = make_float2(fmaf(xmk, c2, xmpk * s2), fmaf(xmk, s2, -xmpk * c2));
    float2 P = make_float2(Vk.x + Vm.x, Vk.y - Vm.y);   // V_k + conj(V_{M-k})
    float2 Q = make_float2(Vk.x - Vm.x, Vk.y + Vm.y);   // V_k - conj(V_{M-k})
    return make_float2(P.x - W.y * Q.x - W.x * Q.y,
                       P.y + W.x * Q.x - W.y * Q.y);
}

__global__ __launch_bounds__(THREADS, 9)
void idct_kernel(const float* __restrict__ x,
                 const float2* __restrict__ expk,
                 float* __restrict__ y) {
    extern __shared__ float2 buf[];   // 2048 float2, in-place via syncs

    const int tid = threadIdx.x;
    const float* xr = x + (size_t)blockIdx.x * NN;
    const float C8 = 0.70710678118654752f;

    // Stage twiddle bases, loaded directly (exact; no pow4 chain):
    //   W_2048^tid    = e^{j*pi*(8*tid)/8192}  = flip(expk[8*tid])
    //   W_2048^{16p}  = e^{j*pi*(128*p)/8192}  = flip(expk[128*p])
    float2 Ew1 = __ldg(&expk[8 * tid]);
    float2 Ew2 = __ldg(&expk[128 * (tid >> 4)]);

    // ---- Z build + radix-16 stage 1 (S=1, p=tid) ----
    // Pair k and k+1024: one W = e^{j*2pi*k/4096} serves both (W' = j*W).
    {
        float2 Z[16];
#pragma unroll
        for (int i = 0; i < 8; i++) {
            int k  = tid + i * THREADS;   // [0, 1024)
            int k2 = k + 1024;            // [1024, 2048)

            float xk   = xr[k];
            float xnk  = (k == 0) ? 0.0f : xr[NN - k];
            float xmk  = xr[MM - k];
            float xmpk = xr[MM + k];
            float2 E1 = __ldg(&expk[k]);
            float2 W  = csqr(csqr(make_float2(E1.x, -E1.y)));   // e^{j*2pi*k/4096}
            Z[i] = z_elem(xk, xnk, xmk, xmpk, E1, W, C8);

            float yk   = xr[k2];
            float ynk  = xr[NN - k2];
            float ymk  = xr[MM - k2];
            float ympk = xr[MM + k2];
            float2 F1 = __ldg(&expk[k2]);
            float2 Wj = make_float2(-W.y, W.x);                  // j*W, exact
            Z[i + 8] = z_elem(yk, ynk, ymk, ympk, F1, Wj, C8);
        }
        idft16_store(buf, Z, make_float2(Ew1.x, -Ew1.y), 16 * tid, 1);
    }
    __syncthreads();

    // ---- radix-16 stage 2 (S=16): in-place (regs -> sync -> write) ----
    {
        float2 a[16];
#pragma unroll
        for (int i = 0; i < 16; i++) a[i] = buf[SW(tid + 128 * i)];
        int p = tid >> 4, q = tid & 15;
        __syncthreads();                            // all reads done before writes
        idft16_store(buf, a, make_float2(Ew2.x, -Ew2.y), q + 256 * p, 16);
    }
    __syncthreads();

    // ---- radix-8 stage 3 (S=256, trivial twiddle) fused with output perm ----
    // Thread handles butterflies b1=tid, b2=255-tid: partner of z_{q+256i}
    // is z_{2047-(q+256i)} = z_{(255-q)+256(7-i)} -> thread-local.
    {
        const int b1 = tid, b2 = 255 - tid;
        float2 a1[8], a2[8], z1[8], z2[8];
#pragma unroll
        for (int i = 0; i < 8; i++) a1[i] = buf[SW(b1 + 256 * i)];
#pragma unroll
        for (int i = 0; i < 8; i++) a2[i] = buf[SW(b2 + 256 * i)];
        idft8(a1, z1);
        idft8(a2, z2);
        // y[4s..4s+3] = {Re z_s, Im z_{2047-s}, Im z_s, Re z_{2047-s}}
        float4* yr = (float4*)(y + (size_t)blockIdx.x * NN);
#pragma unroll
        for (int i = 0; i < 4; i++) {
            yr[b1 + 256 * i] = make_float4(z1[i].x, z2[7 - i].y, z1[i].y, z2[7 - i].x);
            yr[b2 + 256 * i] = make_float4(z2[i].x, z1[7 - i].y, z2[i].y, z1[7 - i].x);
        }
    }
}

extern "C" void kernel_launch(void* const* d_in, const int* in_sizes, int n_in,
                              void* d_out, int out_size) {
    const float*  x    = (const float*)d_in[0];
    const float2* expk = (const float2*)d_in[1];
    float*        y    = (float*)d_out;

    int rows = in_sizes[0] / NN;                 // 4096
    size_t smem_bytes = MM * sizeof(float2);     // 16 KB, single in-place buffer
    idct_kernel<<<rows, THREADS, smem_bytes>>>(x, expk, y);
}